// round 1
// baseline (speedup 1.0000x reference)
#include <cuda_runtime.h>
#include <math.h>

#define NTHREADS 256
#define NNODES   256
#define ROWSTR   129   // 128 + 1 pad: kills 32-way bank conflicts on per-row reads

// shared memory carve (floats)
#define X2_SZ   (NNODES * ROWSTR)        // 33024  node activations [256][129]
#define W_SZ    (16384 + 3 * 128)        // 16768  current-stage weights + b,g,be
#define RED_SZ  768                      // top-2 partials / colmax partials
#define FIN_SZ  192                      // final m1,m2,i1 per channel
#define SMEM_FLOATS (X2_SZ + W_SZ + RED_SZ + FIN_SZ)
#define SMEM_BYTES  (SMEM_FLOATS * 4)

template<int C>
__device__ __forceinline__ void ln_relu(float* h, const float* g, const float* be) {
    float s = 0.f;
#pragma unroll
    for (int i = 0; i < C; i++) s += h[i];
    float mu = s * (1.0f / C);
    float v = 0.f;
#pragma unroll
    for (int i = 0; i < C; i++) { float d = h[i] - mu; v += d * d; }
    float rs = rsqrtf(v * (1.0f / C) + 1e-5f);
#pragma unroll
    for (int i = 0; i < C; i++) {
        float t = (h[i] - mu) * rs * g[i] + be[i];
        h[i] = fmaxf(t, 0.0f);
    }
}

__global__ __launch_bounds__(NTHREADS, 1)
void localgraph_fused_kernel(
    const float* __restrict__ inp,
    const float* __restrict__ W0, const float* __restrict__ b0, const float* __restrict__ g0, const float* __restrict__ be0,
    const float* __restrict__ W1, const float* __restrict__ b1, const float* __restrict__ g1, const float* __restrict__ be1,
    const float* __restrict__ W2, const float* __restrict__ b2, const float* __restrict__ g2, const float* __restrict__ be2,
    const float* __restrict__ W3, const float* __restrict__ b3, const float* __restrict__ g3, const float* __restrict__ be3,
    float* __restrict__ out)
{
    extern __shared__ float smem[];
    float* sx   = smem;                 // [256][129]
    float* sw   = smem + X2_SZ;         // weights region (reused per stage)
    float* sred = sw + W_SZ;            // reduction scratch
    float* sfin = sred + RED_SZ;        // final top-2 per channel

    const int tid = threadIdx.x;
    const int bm  = blockIdx.x;         // (b*M + m)
    const int n   = tid;                // node index

    // ---- load input row (coalesced float4 x2) ----
    float x[8];
    {
        const float4* p = reinterpret_cast<const float4*>(inp + ((size_t)bm * NNODES + n) * 8);
        float4 a = p[0], b = p[1];
        x[0]=a.x; x[1]=a.y; x[2]=a.z; x[3]=a.w;
        x[4]=b.x; x[5]=b.y; x[6]=b.z; x[7]=b.w;
    }

    // ---- stage-1 weights: W0(512) b0 g0 be0 | W1(4096) b1 g1 be1 ----
    for (int i = tid; i < 512;  i += NTHREADS) sw[i]        = W0[i];
    for (int i = tid; i < 64;   i += NTHREADS) { sw[512+i]=b0[i]; sw[576+i]=g0[i]; sw[640+i]=be0[i]; }
    for (int i = tid; i < 4096; i += NTHREADS) sw[704+i]    = W1[i];
    for (int i = tid; i < 64;   i += NTHREADS) { sw[4800+i]=b1[i]; sw[4864+i]=g1[i]; sw[4928+i]=be1[i]; }
    __syncthreads();

    // ---- mlp0: 8 -> 64, LN, ReLU ----
    float h[64];
#pragma unroll
    for (int o = 0; o < 64; o++) h[o] = sw[512 + o];
#pragma unroll
    for (int k = 0; k < 8; k++) {
        float xk = x[k];
        const float4* w4 = reinterpret_cast<const float4*>(&sw[k * 64]);
#pragma unroll
        for (int o = 0; o < 16; o++) {
            float4 w = w4[o];
            h[4*o+0] += xk * w.x; h[4*o+1] += xk * w.y;
            h[4*o+2] += xk * w.z; h[4*o+3] += xk * w.w;
        }
    }
    ln_relu<64>(h, sw + 576, sw + 640);

    // ---- mlp1: 64 -> 64, LN, ReLU ----
    float e2[64];
#pragma unroll
    for (int o = 0; o < 64; o++) e2[o] = sw[4800 + o];
    for (int k = 0; k < 64; k++) {
        float xk = h[k];
        const float4* w4 = reinterpret_cast<const float4*>(&sw[704 + k * 64]);
#pragma unroll
        for (int o = 0; o < 16; o++) {
            float4 w = w4[o];
            e2[4*o+0] += xk * w.x; e2[4*o+1] += xk * w.y;
            e2[4*o+2] += xk * w.z; e2[4*o+3] += xk * w.w;
        }
    }
    ln_relu<64>(e2, sw + 4864, sw + 4928);

#pragma unroll
    for (int d = 0; d < 64; d++) sx[n * ROWSTR + d] = e2[d];
    __syncthreads();

    // ---- exclude-self max over the 256 nodes, per channel (top-2 + argmax) ----
    {
        // 4 chunks of 64 nodes x 64 channels; thread = (chunk, channel)
        const int ch = tid & 63, chunk = tid >> 6;
        float m1 = -INFINITY, m2 = -INFINITY; int i1 = -1;
        const int jb = chunk * 64;
        for (int j = 0; j < 64; j++) {
            float v = sx[(jb + j) * ROWSTR + ch];
            if (v > m1)      { m2 = m1; m1 = v; i1 = jb + j; }
            else if (v > m2) { m2 = v; }
        }
        sred[chunk * 64 + ch]            = m1;
        sred[256 + chunk * 64 + ch]      = m2;
        reinterpret_cast<int*>(sred)[512 + chunk * 64 + ch] = i1;
    }
    __syncthreads();
    if (tid < 64) {
        float m1 = sred[tid], m2 = sred[256 + tid];
        int   i1 = reinterpret_cast<int*>(sred)[512 + tid];
#pragma unroll
        for (int c = 1; c < 4; c++) {
            float a1 = sred[c * 64 + tid], a2 = sred[256 + c * 64 + tid];
            int   ai = reinterpret_cast<int*>(sred)[512 + c * 64 + tid];
            if (a1 > m1) { m2 = fmaxf(m1, a2); m1 = a1; i1 = ai; }
            else         { m2 = fmaxf(m2, a1); }
        }
        sfin[tid] = m1; sfin[64 + tid] = m2;
        reinterpret_cast<int*>(sfin)[128 + tid] = i1;
    }
    __syncthreads();

    // concat: x2[n][64+d] = max(excl_n(d), e2[n][d] - 10000)
#pragma unroll
    for (int d = 0; d < 64; d++) {
        float v  = sx[n * ROWSTR + d];
        float m1 = sfin[d], m2 = sfin[64 + d];
        int   i1 = reinterpret_cast<int*>(sfin)[128 + d];
        float excl = (i1 == n) ? m2 : m1;
        sx[n * ROWSTR + 64 + d] = fmaxf(excl, v - 10000.0f);
    }

    // ---- stage-2 weights: W2(16384) b2 g2 be2 (overwrites stage-1 region) ----
    for (int i = tid; i < 16384; i += NTHREADS) sw[i] = W2[i];
    for (int i = tid; i < 128;   i += NTHREADS) { sw[16384+i]=b2[i]; sw[16512+i]=g2[i]; sw[16640+i]=be2[i]; }
    __syncthreads();

    // ---- mlp2: 128 -> 128, LN, ReLU (reads ONLY own row; writes back in place) ----
    float acc[128];
    float* row = sx + n * ROWSTR;
#pragma unroll
    for (int o = 0; o < 128; o++) acc[o] = sw[16384 + o];
    for (int k = 0; k < 128; k++) {
        float xk = row[k];
        const float4* w4 = reinterpret_cast<const float4*>(&sw[k * 128]);
#pragma unroll
        for (int o = 0; o < 32; o++) {
            float4 w = w4[o];
            acc[4*o+0] += xk * w.x; acc[4*o+1] += xk * w.y;
            acc[4*o+2] += xk * w.z; acc[4*o+3] += xk * w.w;
        }
    }
    ln_relu<128>(acc, sw + 16512, sw + 16640);
#pragma unroll
    for (int d = 0; d < 128; d++) row[d] = acc[d];

    // ---- stage-3 weights: W3 b3 g3 be3 ----
    __syncthreads();   // everyone done reading W2
    for (int i = tid; i < 16384; i += NTHREADS) sw[i] = W3[i];
    for (int i = tid; i < 128;   i += NTHREADS) { sw[16384+i]=b3[i]; sw[16512+i]=g3[i]; sw[16640+i]=be3[i]; }
    __syncthreads();

    // ---- mlp3: 128 -> 128, LN, ReLU ----
#pragma unroll
    for (int o = 0; o < 128; o++) acc[o] = sw[16384 + o];
    for (int k = 0; k < 128; k++) {
        float xk = row[k];
        const float4* w4 = reinterpret_cast<const float4*>(&sw[k * 128]);
#pragma unroll
        for (int o = 0; o < 32; o++) {
            float4 w = w4[o];
            acc[4*o+0] += xk * w.x; acc[4*o+1] += xk * w.y;
            acc[4*o+2] += xk * w.z; acc[4*o+3] += xk * w.w;
        }
    }
    ln_relu<128>(acc, sw + 16512, sw + 16640);
#pragma unroll
    for (int d = 0; d < 128; d++) row[d] = acc[d];
    __syncthreads();

    // ---- final: out[:,:,d] = out[:,:,128+d] = max_n e4[n][d]
    // (max over n of the exclude-self neighborhood equals the plain column max:
    //  for any n != argmax, excl = m1, and x - 10000 < m1 always)
    {
        const int d = tid & 127, chunk = tid >> 7;   // 2 chunks x 128 nodes
        float m = -INFINITY;
        const int jb = chunk * 128;
        for (int j = 0; j < 128; j++) m = fmaxf(m, sx[(jb + j) * ROWSTR + d]);
        sred[chunk * 128 + d] = m;
    }
    __syncthreads();
    if (tid < 128) {
        float m = fmaxf(sred[tid], sred[128 + tid]);
        out[(size_t)bm * 256 + tid]       = m;
        out[(size_t)bm * 256 + 128 + tid] = m;
    }
}

extern "C" void kernel_launch(void* const* d_in, const int* in_sizes, int n_in,
                              void* d_out, int out_size)
{
    // Identify input_states by its unique element count; take the 16 weight
    // tensors in their relative order (robust to metadata ordering).
    const int INPUT_ELEMS = 8 * 128 * 256 * 8;   // 2,097,152
    const float* inp = nullptr;
    const float* w[16];
    int wi = 0;
    for (int i = 0; i < n_in; i++) {
        if (in_sizes[i] == INPUT_ELEMS) inp = (const float*)d_in[i];
        else if (wi < 16)               w[wi++] = (const float*)d_in[i];
    }

    cudaFuncSetAttribute(localgraph_fused_kernel,
                         cudaFuncAttributeMaxDynamicSharedMemorySize, SMEM_BYTES);

    localgraph_fused_kernel<<<8 * 128, NTHREADS, SMEM_BYTES>>>(
        inp,
        w[0],  w[1],  w[2],  w[3],
        w[4],  w[5],  w[6],  w[7],
        w[8],  w[9],  w[10], w[11],
        w[12], w[13], w[14], w[15],
        (float*)d_out);
}